// round 16
// baseline (speedup 1.0000x reference)
#include <cuda_runtime.h>
#include <cuda_fp16.h>
#include <math.h>

#define Bn 16
#define Tn 1024
#define Cn 384
#define Hn 6
#define Dn 64
#define BH (Bn*Hn)

#define LDA 36    // 32-col m-major tiles (qkv/proj): frag addr ~ 4g+t4, conflict-free
#define LDB 72    // k-major B tiles (qkv): frag addr ~ 8t4+g, conflict-free
#define LDSH 72   // attn half tiles (Q/K/P), stride in halves: word idx ~ 4g+t4, conflict-free
#define LDVH 72   // attn Vt tile (halves)

// scratch (device globals; no allocs allowed)
__device__ __half g_qh[BH*Tn*Dn];    // fp16 q, row-major [bh][t][d]
__device__ __half g_kh[BH*Tn*Dn];    // fp16 k, row-major [bh][t][d]
__device__ __half g_vt[BH*Dn*Tn];    // fp16 v, TRANSPOSED [bh][d][t]
__device__ float  g_attn[BH*Tn*Dn];  // fp32 tf32-rounded (proj operand)
__device__ float  g_xr[Bn*Tn*Cn];    // tf32-rounded inputs
__device__ float  g_wqr[Hn*Cn*Dn];
__device__ float  g_wkr[Hn*Cn*Dn];
__device__ float  g_wvr[Hn*Cn*Dn];
__device__ float  g_wpr[Cn*Cn];

// ---------------------------------------------------------------------------
// helpers
// ---------------------------------------------------------------------------
__device__ __forceinline__ float f2tf(float f) {
    unsigned r;
    asm("cvt.rna.tf32.f32 %0, %1;" : "=r"(r) : "f"(f));
    return __uint_as_float(r);
}
__device__ __forceinline__ float4 f2tf4(float4 v) {
    return make_float4(f2tf(v.x), f2tf(v.y), f2tf(v.z), f2tf(v.w));
}
// tf32 m16n8k8 (qkv/proj)
__device__ __forceinline__ void mma8(float* d, const unsigned* a, const unsigned* b) {
    asm volatile(
        "mma.sync.aligned.m16n8k8.row.col.f32.tf32.tf32.f32 "
        "{%0,%1,%2,%3},{%4,%5,%6,%7},{%8,%9},{%0,%1,%2,%3};"
        : "+f"(d[0]), "+f"(d[1]), "+f"(d[2]), "+f"(d[3])
        : "r"(a[0]), "r"(a[1]), "r"(a[2]), "r"(a[3]), "r"(b[0]), "r"(b[1]));
}
// fp16 m16n8k16 (attention): a,b packed half2, fp32 accum
__device__ __forceinline__ void mma16h(float* d, const unsigned* a, const unsigned* b) {
    asm volatile(
        "mma.sync.aligned.m16n8k16.row.col.f32.f16.f16.f32 "
        "{%0,%1,%2,%3},{%4,%5,%6,%7},{%8,%9},{%0,%1,%2,%3};"
        : "+f"(d[0]), "+f"(d[1]), "+f"(d[2]), "+f"(d[3])
        : "r"(a[0]), "r"(a[1]), "r"(a[2]), "r"(a[3]), "r"(b[0]), "r"(b[1]));
}
__device__ __forceinline__ unsigned fau(float f) { return __float_as_uint(f); }
__device__ __forceinline__ unsigned ldh2(const __half* p) {
    return *reinterpret_cast<const unsigned*>(p);
}

__device__ __forceinline__ void cp16(float* s, const float* g) {
    unsigned ss = (unsigned)__cvta_generic_to_shared(s);
    asm volatile("cp.async.ca.shared.global [%0], [%1], 16;\n" :: "r"(ss), "l"(g));
}
__device__ __forceinline__ void cp16h(__half* s, const __half* g) {
    unsigned ss = (unsigned)__cvta_generic_to_shared(s);
    asm volatile("cp.async.ca.shared.global [%0], [%1], 16;\n" :: "r"(ss), "l"(g));
}
#define CP_COMMIT asm volatile("cp.async.commit_group;\n" ::: "memory")
#define CP_WAIT0  asm volatile("cp.async.wait_group 0;\n" ::: "memory")

// ---------------------------------------------------------------------------
// Kernel 0: fused tf32-round prepass (one launch for all 5 arrays)
// ---------------------------------------------------------------------------
#define N4_X  (Bn*Tn*Cn/4)
#define N4_W  (Hn*Cn*Dn/4)
#define N4_P  (Cn*Cn/4)
#define N4_TOT (N4_X + 3*N4_W + N4_P)

__global__ void round_all(const float4* __restrict__ x,
                          const float4* __restrict__ wq,
                          const float4* __restrict__ wk,
                          const float4* __restrict__ wv,
                          const float4* __restrict__ wp)
{
    int j = blockIdx.x * 256 + threadIdx.x;
    const float4* s; float4* d;
    if (j < N4_X)                { s = x;  d = (float4*)g_xr; }
    else if ((j -= N4_X) < N4_W) { s = wq; d = (float4*)g_wqr; }
    else if ((j -= N4_W) < N4_W) { s = wk; d = (float4*)g_wkr; }
    else if ((j -= N4_W) < N4_W) { s = wv; d = (float4*)g_wvr; }
    else if ((j -= N4_W) < N4_P) { s = wp; d = (float4*)g_wpr; }
    else return;
    d[j] = f2tf4(s[j]);
}

// ---------------------------------------------------------------------------
// Kernel 1: QKV projection (R10 config, tf32 HMMA). Block 256m x 64n, 8 warps
// m32, cp.async 2-stage. grid = (64, 18), block 256.
// Epilogue: q,k -> fp16 row-major; v -> fp16 TRANSPOSED [d][t].
// ---------------------------------------------------------------------------
__global__ void __launch_bounds__(256, 2)
qkv_kernel()
{
    extern __shared__ __align__(16) float smq[];
    float* Xs = smq;                    // [2][256*LDA]
    float* Ws = smq + 2 * 256 * LDA;    // [2][32*LDB]

    const int mt  = blockIdx.x;
    const int nt  = blockIdx.y;
    const int mat = nt / Hn;
    const int h   = nt % Hn;
    const float* w = (mat == 0 ? g_wqr : (mat == 1 ? g_wkr : g_wvr)) + h * Cn * Dn;

    const int tid  = threadIdx.x;
    const int warp = tid >> 5, lane = tid & 31;
    const int g = lane >> 2, t4 = lane & 3;
    const int m0 = mt * 256;
    const int wm = warp * 32;

    float acc[2][8][4] = {};

    auto load_stage = [&](int it, int st) {
        const int k0 = it * 32;
        float* Xd = Xs + st * 256 * LDA;
        float* Wd = Ws + st * 32 * LDB;
        #pragma unroll
        for (int i = 0; i < 8; i++) {
            int f = tid + i * 256;
            int r = f >> 3, c = (f & 7) * 4;
            cp16(&Xd[r * LDA + c], &g_xr[(m0 + r) * Cn + k0 + c]);
        }
        #pragma unroll
        for (int i = 0; i < 2; i++) {
            int f = tid + i * 256;
            int r = f >> 4, c = (f & 15) * 4;
            cp16(&Wd[r * LDB + c], &w[(k0 + r) * Dn + c]);
        }
        CP_COMMIT;
    };

    load_stage(0, 0);
    for (int it = 0; it < 12; it++) {
        const int cur = it & 1;
        CP_WAIT0;
        __syncthreads();
        if (it + 1 < 12) load_stage(it + 1, cur ^ 1);

        const float* Xc = Xs + cur * 256 * LDA;
        const float* Wc = Ws + cur * 32 * LDB;
        #pragma unroll
        for (int kk = 0; kk < 32; kk += 8) {
            unsigned a[2][4];
            #pragma unroll
            for (int ms = 0; ms < 2; ms++) {
                const float* Ar = &Xc[(wm + ms * 16 + g) * LDA + kk];
                a[ms][0] = fau(Ar[t4]);           a[ms][2] = fau(Ar[t4 + 4]);
                a[ms][1] = fau(Ar[8 * LDA + t4]); a[ms][3] = fau(Ar[8 * LDA + t4 + 4]);
            }
            #pragma unroll
            for (int n = 0; n < 8; n++) {
                unsigned b[2];
                b[0] = fau(Wc[(kk + t4) * LDB + n * 8 + g]);
                b[1] = fau(Wc[(kk + t4 + 4) * LDB + n * 8 + g]);
                mma8(acc[0][n], a[0], b);
                mma8(acc[1][n], a[1], b);
            }
        }
    }

    // epilogue: fp16 outputs (same 10-bit mantissa as tf32)
    #pragma unroll
    for (int ms = 0; ms < 2; ms++)
        #pragma unroll
        for (int rh = 0; rh < 2; rh++) {
            int m = m0 + wm + ms * 16 + rh * 8 + g;
            int b = m >> 10, t = m & 1023;
            if (mat < 2) {
                __half* dst = (mat == 0 ? g_qh : g_kh) + ((b * Hn + h) * Tn + t) * Dn;
                #pragma unroll
                for (int n = 0; n < 8; n++)
                    *reinterpret_cast<__half2*>(&dst[n * 8 + 2 * t4]) =
                        __floats2half2_rn(acc[ms][n][2 * rh], acc[ms][n][2 * rh + 1]);
            } else {
                __half* dst = g_vt + (b * Hn + h) * Dn * Tn;
                #pragma unroll
                for (int n = 0; n < 8; n++) {
                    int d0 = n * 8 + 2 * t4;
                    dst[d0 * Tn + t]       = __float2half_rn(acc[ms][n][2 * rh]);
                    dst[(d0 + 1) * Tn + t] = __float2half_rn(acc[ms][n][2 * rh + 1]);
                }
            }
        }
}

// ---------------------------------------------------------------------------
// Kernel 2: flash attention in fp16 (m16n8k16, fp32 accum). No-max softmax,
// deferred 1/l. BLOCK_M=128, BLOCK_N=64, 4 warps m32, 2-stage cp.async K/V.
// All fragment operand pairs are adjacent half2 -> single LDS.32 each.
// smem = (128*LDSH + 2*64*LDSH + 2*64*LDVH)*2 = 55296 B. grid=(8,96), block 128.
// ---------------------------------------------------------------------------
__global__ void __launch_bounds__(128, 2)
attn_kernel()
{
    extern __shared__ __align__(16) __half smh[];
    __half* QP = smh;                      // [128][LDSH]: Q, then P (aliased)
    __half* Ks = QP + 128 * LDSH;          // [2][64][LDSH]
    __half* Vs = Ks + 2 * 64 * LDSH;       // [2][64][LDVH]  (rows = d, cols = s)

    const int qt = blockIdx.x;
    const int bh = blockIdx.y;
    const __half* qb = g_qh + bh * Tn * Dn;
    const __half* kb = g_kh + bh * Tn * Dn;
    const __half* vt = g_vt + bh * Dn * Tn;

    const int tid  = threadIdx.x;
    const int warp = tid >> 5, lane = tid & 31;
    const int g = lane >> 2, t4 = lane & 3;
    const int wm = warp * 32;
    const float scale = 0.05103103630798287f;   // 1/sqrt(384)

    auto load_kv = [&](int kt, int st) {
        __half* Kd = Ks + st * 64 * LDSH;
        __half* Vd = Vs + st * 64 * LDVH;
        #pragma unroll
        for (int i = 0; i < 4; i++) {
            int f = tid + i * 128;                 // 512 chunks of 16B (8 halves)
            int r = f >> 3, c = (f & 7) * 8;
            cp16h(&Kd[r * LDSH + c], &kb[(kt * 64 + r) * Dn + c]);
            cp16h(&Vd[r * LDVH + c], &vt[r * Tn + kt * 64 + c]);
        }
        CP_COMMIT;
    };

    // stage Q (plain 16B copies); start K/V pipeline
    #pragma unroll
    for (int i = 0; i < 8; i++) {
        int f = tid + i * 128;
        int r = f >> 3, c = (f & 7) * 8;
        *reinterpret_cast<float4*>(&QP[r * LDSH + c]) =
            *reinterpret_cast<const float4*>(&qb[(qt * 128 + r) * Dn + c]);
    }
    load_kv(0, 0);
    __syncthreads();

    // hoist Q fragments (a0=[g][2t4], a1=[g+8][2t4], a2=[g][2t4+8], a3=[g+8][2t4+8])
    unsigned qf[4][2][4];
    #pragma unroll
    for (int kk = 0; kk < 4; kk++)
        #pragma unroll
        for (int ms = 0; ms < 2; ms++) {
            const __half* r0 = &QP[(wm + ms * 16 + g) * LDSH + kk * 16 + 2 * t4];
            const __half* r1 = r0 + 8 * LDSH;
            qf[kk][ms][0] = ldh2(r0);     qf[kk][ms][2] = ldh2(r0 + 8);
            qf[kk][ms][1] = ldh2(r1);     qf[kk][ms][3] = ldh2(r1 + 8);
        }

    float l_r[2][2] = {};    // per-thread partial row sums (reduced at epilogue)
    float o[2][8][4] = {};

    for (int kt = 0; kt < Tn / 64; kt++) {
        const int cur = kt & 1;
        CP_WAIT0;
        __syncthreads();                 // tile kt visible; prev buffer free
        if (kt + 1 < Tn / 64) load_kv(kt + 1, cur ^ 1);

        const __half* Kc = Ks + cur * 64 * LDSH;
        const __half* Vc = Vs + cur * 64 * LDVH;

        // S = Q K^T : warp m32 x n64, k64 in 4 mma-k16 steps
        float s[2][8][4] = {};
        #pragma unroll
        for (int kk = 0; kk < 4; kk++) {
            #pragma unroll
            for (int n = 0; n < 8; n++) {
                const __half* kp = &Kc[(n * 8 + g) * LDSH + kk * 16 + 2 * t4];
                unsigned b[2] = { ldh2(kp), ldh2(kp + 8) };
                mma16h(s[0][n], qf[kk][0], b);
                mma16h(s[1][n], qf[kk][1], b);
            }
        }

        // softmax numerator: p = exp(s*scale); P written as half2 (warp-private)
        #pragma unroll
        for (int ms = 0; ms < 2; ms++) {
            float rs0 = 0.f, rs1 = 0.f;
            #pragma unroll
            for (int n = 0; n < 8; n++) {
                float p0 = __expf(s[ms][n][0] * scale);
                float p1 = __expf(s[ms][n][1] * scale);
                float p2 = __expf(s[ms][n][2] * scale);
                float p3 = __expf(s[ms][n][3] * scale);
                rs0 += p0 + p1;
                rs1 += p2 + p3;
                *reinterpret_cast<__half2*>(
                    &QP[(wm + ms * 16 + g) * LDSH + n * 8 + 2 * t4]) =
                    __floats2half2_rn(p0, p1);
                *reinterpret_cast<__half2*>(
                    &QP[(wm + ms * 16 + g + 8) * LDSH + n * 8 + 2 * t4]) =
                    __floats2half2_rn(p2, p3);
            }
            l_r[ms][0] += rs0;
            l_r[ms][1] += rs1;
        }
        __syncwarp();        // P rows are warp-private: warp barrier suffices

        // O += P V : A = P[m][s], B = V[s][d] from Vt[d][s]
        #pragma unroll
        for (int kk = 0; kk < 4; kk++) {
            unsigned a[2][4];
            #pragma unroll
            for (int ms = 0; ms < 2; ms++) {
                const __half* r0 = &QP[(wm + ms * 16 + g) * LDSH + kk * 16 + 2 * t4];
                const __half* r1 = r0 + 8 * LDSH;
                a[ms][0] = ldh2(r0);     a[ms][2] = ldh2(r0 + 8);
                a[ms][1] = ldh2(r1);     a[ms][3] = ldh2(r1 + 8);
            }
            #pragma unroll
            for (int n = 0; n < 8; n++) {
                const __half* vp = &Vc[(n * 8 + g) * LDVH + kk * 16 + 2 * t4];
                unsigned b[2] = { ldh2(vp), ldh2(vp + 8) };
                mma16h(o[0][n], a[0], b);
                mma16h(o[1][n], a[1], b);
            }
        }
    }

    // epilogue: reduce l across 4-lane group, normalize, tf32-round for proj
    #pragma unroll
    for (int ms = 0; ms < 2; ms++)
        #pragma unroll
        for (int rh = 0; rh < 2; rh++) {
            float l = l_r[ms][rh];
            l += __shfl_xor_sync(0xffffffffu, l, 1);
            l += __shfl_xor_sync(0xffffffffu, l, 2);
            float inv = 1.f / l;
            int r = qt * 128 + wm + ms * 16 + rh * 8 + g;
            float* orow = g_attn + (bh * Tn + r) * Dn;
            #pragma unroll
            for (int n = 0; n < 8; n++)
                *reinterpret_cast<float2*>(&orow[n * 8 + 2 * t4]) =
                    make_float2(f2tf(o[ms][n][2 * rh] * inv),
                                f2tf(o[ms][n][2 * rh + 1] * inv));
        }
}

// ---------------------------------------------------------------------------
// Kernel 3: output projection (EXACT R10 config, tf32). Block 256m x 64n,
// 8 warps m32, cp.async 2-stage. grid = (64, 6).
// ---------------------------------------------------------------------------
__global__ void __launch_bounds__(256, 2)
proj_kernel(const float* __restrict__ bp, float* __restrict__ out)
{
    extern __shared__ __align__(16) float smp[];
    float* As = smp;                    // [2][256*LDA]
    float* Wn = smp + 2 * 256 * LDA;    // [2][64*LDA]

    const int mt = blockIdx.x;
    const int nt = blockIdx.y;
    const int tid  = threadIdx.x;
    const int warp = tid >> 5, lane = tid & 31;
    const int g = lane >> 2, t4 = lane & 3;
    const int m0 = mt * 256, n0 = nt * 64;
    const int wm = warp * 32;

    float acc[2][8][4] = {};

    auto load_stage = [&](int it, int st) {
        const int k0 = it * 32;
        const int h  = k0 >> 6;
        const int d0 = k0 & 63;
        float* Ad = As + st * 256 * LDA;
        float* Wd = Wn + st * 64 * LDA;
        #pragma unroll
        for (int i = 0; i < 8; i++) {
            int f = tid + i * 256;
            int r = f >> 3, c = (f & 7) * 4;
            int m = m0 + r, b = m >> 10, t = m & 1023;
            cp16(&Ad[r * LDA + c], &g_attn[((b * Hn + h) * Tn + t) * Dn + d0 + c]);
        }
        #pragma unroll
        for (int i = 0; i < 2; i++) {
            int f = tid + i * 256;
            int r = f >> 3, c = (f & 7) * 4;
            cp16(&Wd[r * LDA + c], &g_wpr[(n0 + r) * Cn + k0 + c]);
        }
        CP_COMMIT;
    };

    load_stage(0, 0);
    for (int it = 0; it < 12; it++) {
        const int cur = it & 1;
        CP_WAIT0;
        __syncthreads();
        if (it + 1 < 12) load_stage(it + 1, cur ^ 1);

        const float* Ac = As + cur * 256 * LDA;
        const float* Wc = Wn + cur * 64 * LDA;
        #pragma unroll
        for (int kk = 0; kk < 32; kk += 8) {
            unsigned a[2][4];
            #pragma unroll
            for (int ms = 0; ms < 2; ms++) {
                const float* Ar = &Ac[(wm + ms * 16 + g) * LDA + kk];
                a[ms][0] = fau(Ar[t4]);           a[ms][2] = fau(Ar[t4 + 4]);
                a[ms][1] = fau(Ar[8 * LDA + t4]); a[ms][3] = fau(Ar[8 * LDA + t4 + 4]);
            }
            #pragma unroll
            for (int n = 0; n < 8; n++) {
                unsigned b[2];
                b[0] = fau(Wc[(n * 8 + g) * LDA + kk + t4]);
                b[1] = fau(Wc[(n * 8 + g) * LDA + kk + t4 + 4]);
                mma8(acc[0][n], a[0], b);
                mma8(acc[1][n], a[1], b);
            }
        }
    }

    #pragma unroll
    for (int ms = 0; ms < 2; ms++)
        #pragma unroll
        for (int rh = 0; rh < 2; rh++) {
            int m = m0 + wm + ms * 16 + rh * 8 + g;
            #pragma unroll
            for (int n = 0; n < 8; n++) {
                int c = n0 + n * 8 + 2 * t4;
                *reinterpret_cast<float2*>(&out[m * Cn + c]) =
                    make_float2(acc[ms][n][2 * rh] + bp[c],
                                acc[ms][n][2 * rh + 1] + bp[c + 1]);
            }
        }
}

// ---------------------------------------------------------------------------
extern "C" void kernel_launch(void* const* d_in, const int* in_sizes, int n_in,
                              void* d_out, int out_size)
{
    const float* x  = (const float*)d_in[0];
    const float* wq = (const float*)d_in[1];
    const float* wk = (const float*)d_in[2];
    const float* wv = (const float*)d_in[3];
    const float* wp = (const float*)d_in[4];
    const float* bp = (const float*)d_in[5];
    float* out = (float*)d_out;

    round_all<<<(N4_TOT + 255) / 256, 256>>>(
        (const float4*)x, (const float4*)wq, (const float4*)wk,
        (const float4*)wv, (const float4*)wp);

    const int qkv_smem = 2 * (256 * LDA + 32 * LDB) * (int)sizeof(float);   // 92160
    cudaFuncSetAttribute(qkv_kernel,
                         cudaFuncAttributeMaxDynamicSharedMemorySize, qkv_smem);
    qkv_kernel<<<dim3(64, 18), 256, qkv_smem>>>();

    const int attn_smem =
        (128 * LDSH + 2 * 64 * LDSH + 2 * 64 * LDVH) * (int)sizeof(__half); // 55296
    cudaFuncSetAttribute(attn_kernel,
                         cudaFuncAttributeMaxDynamicSharedMemorySize, attn_smem);
    attn_kernel<<<dim3(Tn / 128, BH), 128, attn_smem>>>();

    const int proj_smem = 2 * (256 * LDA + 64 * LDA) * (int)sizeof(float);  // 92160
    cudaFuncSetAttribute(proj_kernel,
                         cudaFuncAttributeMaxDynamicSharedMemorySize, proj_smem);
    proj_kernel<<<dim3(64, 6), 256, proj_smem>>>(bp, out);
}

// round 17
// speedup vs baseline: 1.4898x; 1.4898x over previous
#include <cuda_runtime.h>
#include <cuda_fp16.h>
#include <math.h>

#define Bn 16
#define Tn 1024
#define Cn 384
#define Hn 6
#define Dn 64
#define BH (Bn*Hn)

#define LDA 36    // 32-col m-major tiles (qkv/proj): frag addr ~ 4g+t4, conflict-free
#define LDB 72    // k-major B tiles (qkv): frag addr ~ 8t4+g, conflict-free
#define LDSH 72   // attn half tiles (Q/K/P), stride in halves: word idx ~ 4g+t4, conflict-free
#define LDVH 72   // attn Vt tile (halves)
#define LTT 66    // vtrans smem tile stride (halves)

// scratch (device globals; no allocs allowed)
__device__ __half g_qh[BH*Tn*Dn];    // fp16 q, row-major [bh][t][d]
__device__ __half g_kh[BH*Tn*Dn];    // fp16 k, row-major [bh][t][d]
__device__ __half g_vh[BH*Tn*Dn];    // fp16 v, row-major [bh][t][d]
__device__ __half g_vt[BH*Dn*Tn];    // fp16 v, TRANSPOSED [bh][d][t]
__device__ float  g_attn[BH*Tn*Dn];  // fp32 tf32-rounded (proj operand)
__device__ float  g_xr[Bn*Tn*Cn];    // tf32-rounded inputs
__device__ float  g_wqr[Hn*Cn*Dn];
__device__ float  g_wkr[Hn*Cn*Dn];
__device__ float  g_wvr[Hn*Cn*Dn];
__device__ float  g_wpr[Cn*Cn];

// ---------------------------------------------------------------------------
// helpers
// ---------------------------------------------------------------------------
__device__ __forceinline__ float f2tf(float f) {
    unsigned r;
    asm("cvt.rna.tf32.f32 %0, %1;" : "=r"(r) : "f"(f));
    return __uint_as_float(r);
}
__device__ __forceinline__ float4 f2tf4(float4 v) {
    return make_float4(f2tf(v.x), f2tf(v.y), f2tf(v.z), f2tf(v.w));
}
// tf32 m16n8k8 (qkv/proj)
__device__ __forceinline__ void mma8(float* d, const unsigned* a, const unsigned* b) {
    asm volatile(
        "mma.sync.aligned.m16n8k8.row.col.f32.tf32.tf32.f32 "
        "{%0,%1,%2,%3},{%4,%5,%6,%7},{%8,%9},{%0,%1,%2,%3};"
        : "+f"(d[0]), "+f"(d[1]), "+f"(d[2]), "+f"(d[3])
        : "r"(a[0]), "r"(a[1]), "r"(a[2]), "r"(a[3]), "r"(b[0]), "r"(b[1]));
}
// fp16 m16n8k16 (attention): a,b packed half2, fp32 accum
__device__ __forceinline__ void mma16h(float* d, const unsigned* a, const unsigned* b) {
    asm volatile(
        "mma.sync.aligned.m16n8k16.row.col.f32.f16.f16.f32 "
        "{%0,%1,%2,%3},{%4,%5,%6,%7},{%8,%9},{%0,%1,%2,%3};"
        : "+f"(d[0]), "+f"(d[1]), "+f"(d[2]), "+f"(d[3])
        : "r"(a[0]), "r"(a[1]), "r"(a[2]), "r"(a[3]), "r"(b[0]), "r"(b[1]));
}
__device__ __forceinline__ unsigned fau(float f) { return __float_as_uint(f); }
__device__ __forceinline__ unsigned ldh2(const __half* p) {
    return *reinterpret_cast<const unsigned*>(p);
}

__device__ __forceinline__ void cp16(float* s, const float* g) {
    unsigned ss = (unsigned)__cvta_generic_to_shared(s);
    asm volatile("cp.async.ca.shared.global [%0], [%1], 16;\n" :: "r"(ss), "l"(g));
}
__device__ __forceinline__ void cp16h(__half* s, const __half* g) {
    unsigned ss = (unsigned)__cvta_generic_to_shared(s);
    asm volatile("cp.async.ca.shared.global [%0], [%1], 16;\n" :: "r"(ss), "l"(g));
}
#define CP_COMMIT asm volatile("cp.async.commit_group;\n" ::: "memory")
#define CP_WAIT0  asm volatile("cp.async.wait_group 0;\n" ::: "memory")

// ---------------------------------------------------------------------------
// Kernel 0: fused tf32-round prepass (one launch for all 5 arrays)
// ---------------------------------------------------------------------------
#define N4_X  (Bn*Tn*Cn/4)
#define N4_W  (Hn*Cn*Dn/4)
#define N4_P  (Cn*Cn/4)
#define N4_TOT (N4_X + 3*N4_W + N4_P)

__global__ void round_all(const float4* __restrict__ x,
                          const float4* __restrict__ wq,
                          const float4* __restrict__ wk,
                          const float4* __restrict__ wv,
                          const float4* __restrict__ wp)
{
    int j = blockIdx.x * 256 + threadIdx.x;
    const float4* s; float4* d;
    if (j < N4_X)                { s = x;  d = (float4*)g_xr; }
    else if ((j -= N4_X) < N4_W) { s = wq; d = (float4*)g_wqr; }
    else if ((j -= N4_W) < N4_W) { s = wk; d = (float4*)g_wkr; }
    else if ((j -= N4_W) < N4_W) { s = wv; d = (float4*)g_wvr; }
    else if ((j -= N4_W) < N4_P) { s = wp; d = (float4*)g_wpr; }
    else return;
    d[j] = f2tf4(s[j]);
}

// ---------------------------------------------------------------------------
// Kernel 1: QKV projection (R10 config, tf32 HMMA). Block 256m x 64n, 8 warps
// m32, cp.async 2-stage. grid = (64, 18), block 256.
// Epilogue: q,k,v ALL fp16 row-major (vectorized half2 stores).
// ---------------------------------------------------------------------------
__global__ void __launch_bounds__(256, 2)
qkv_kernel()
{
    extern __shared__ __align__(16) float smq[];
    float* Xs = smq;                    // [2][256*LDA]
    float* Ws = smq + 2 * 256 * LDA;    // [2][32*LDB]

    const int mt  = blockIdx.x;
    const int nt  = blockIdx.y;
    const int mat = nt / Hn;
    const int h   = nt % Hn;
    const float* w = (mat == 0 ? g_wqr : (mat == 1 ? g_wkr : g_wvr)) + h * Cn * Dn;
    __half* outbase = (mat == 0 ? g_qh : (mat == 1 ? g_kh : g_vh));

    const int tid  = threadIdx.x;
    const int warp = tid >> 5, lane = tid & 31;
    const int g = lane >> 2, t4 = lane & 3;
    const int m0 = mt * 256;
    const int wm = warp * 32;

    float acc[2][8][4] = {};

    auto load_stage = [&](int it, int st) {
        const int k0 = it * 32;
        float* Xd = Xs + st * 256 * LDA;
        float* Wd = Ws + st * 32 * LDB;
        #pragma unroll
        for (int i = 0; i < 8; i++) {
            int f = tid + i * 256;
            int r = f >> 3, c = (f & 7) * 4;
            cp16(&Xd[r * LDA + c], &g_xr[(m0 + r) * Cn + k0 + c]);
        }
        #pragma unroll
        for (int i = 0; i < 2; i++) {
            int f = tid + i * 256;
            int r = f >> 4, c = (f & 15) * 4;
            cp16(&Wd[r * LDB + c], &w[(k0 + r) * Dn + c]);
        }
        CP_COMMIT;
    };

    load_stage(0, 0);
    for (int it = 0; it < 12; it++) {
        const int cur = it & 1;
        CP_WAIT0;
        __syncthreads();
        if (it + 1 < 12) load_stage(it + 1, cur ^ 1);

        const float* Xc = Xs + cur * 256 * LDA;
        const float* Wc = Ws + cur * 32 * LDB;
        #pragma unroll
        for (int kk = 0; kk < 32; kk += 8) {
            unsigned a[2][4];
            #pragma unroll
            for (int ms = 0; ms < 2; ms++) {
                const float* Ar = &Xc[(wm + ms * 16 + g) * LDA + kk];
                a[ms][0] = fau(Ar[t4]);           a[ms][2] = fau(Ar[t4 + 4]);
                a[ms][1] = fau(Ar[8 * LDA + t4]); a[ms][3] = fau(Ar[8 * LDA + t4 + 4]);
            }
            #pragma unroll
            for (int n = 0; n < 8; n++) {
                unsigned b[2];
                b[0] = fau(Wc[(kk + t4) * LDB + n * 8 + g]);
                b[1] = fau(Wc[(kk + t4 + 4) * LDB + n * 8 + g]);
                mma8(acc[0][n], a[0], b);
                mma8(acc[1][n], a[1], b);
            }
        }
    }

    // epilogue: fp16 row-major, half2 stores (fp16 mantissa == tf32 mantissa)
    #pragma unroll
    for (int ms = 0; ms < 2; ms++)
        #pragma unroll
        for (int rh = 0; rh < 2; rh++) {
            int m = m0 + wm + ms * 16 + rh * 8 + g;
            int b = m >> 10, t = m & 1023;
            __half* dst = outbase + ((b * Hn + h) * Tn + t) * Dn;
            #pragma unroll
            for (int n = 0; n < 8; n++)
                *reinterpret_cast<__half2*>(&dst[n * 8 + 2 * t4]) =
                    __floats2half2_rn(acc[ms][n][2 * rh], acc[ms][n][2 * rh + 1]);
        }
}

// ---------------------------------------------------------------------------
// Kernel 1b: V transpose, g_vh[bh][t][d] -> g_vt[bh][d][t].
// 64x64 half tiles via smem (stride 66), coalesced float4 on both gmem sides.
// grid = (16, 96), block 256. ~25 MB round trip ≈ 6 us.
// ---------------------------------------------------------------------------
__global__ void __launch_bounds__(256, 4)
vtrans_kernel()
{
    __shared__ __half tile[64 * LTT];
    const int tt = blockIdx.x;          // t-tile 0..15
    const int bh = blockIdx.y;          // 0..95
    const __half* src = g_vh + (bh * Tn + tt * 64) * Dn;
    __half* dst = g_vt + bh * Dn * Tn + tt * 64;
    const int tid = threadIdx.x;

    #pragma unroll
    for (int i = 0; i < 2; i++) {       // load 64 rows x 64 halves
        int f = tid + i * 256;
        int r = f >> 3, c = (f & 7) * 8;
        float4 v = *reinterpret_cast<const float4*>(&src[r * Dn + c]);
        const unsigned* u = reinterpret_cast<const unsigned*>(&v);
        #pragma unroll
        for (int j = 0; j < 4; j++)
            *reinterpret_cast<unsigned*>(&tile[r * LTT + c + 2 * j]) = u[j];
    }
    __syncthreads();

    #pragma unroll
    for (int i = 0; i < 2; i++) {       // write 64 d-rows x 64 t-cols
        int f = tid + i * 256;
        int dr = f >> 3, tc = (f & 7) * 8;
        __half outv[8];
        #pragma unroll
        for (int j = 0; j < 8; j++)
            outv[j] = tile[(tc + j) * LTT + dr];
        *reinterpret_cast<float4*>(&dst[dr * Tn + tc]) =
            *reinterpret_cast<const float4*>(outv);
    }
}

// ---------------------------------------------------------------------------
// Kernel 2: flash attention in fp16 (m16n8k16, fp32 accum) — verified-correct
// R16 kernel, unchanged. No-max softmax, deferred 1/l. BLOCK_M=128,
// BLOCK_N=64, 4 warps m32, 2-stage cp.async K/V.
// smem = (128*LDSH + 2*64*LDSH + 2*64*LDVH)*2 = 55296 B. grid=(8,96), block 128.
// ---------------------------------------------------------------------------
__global__ void __launch_bounds__(128, 2)
attn_kernel()
{
    extern __shared__ __align__(16) __half smh[];
    __half* QP = smh;                      // [128][LDSH]: Q, then P (aliased)
    __half* Ks = QP + 128 * LDSH;          // [2][64][LDSH]
    __half* Vs = Ks + 2 * 64 * LDSH;       // [2][64][LDVH]  (rows = d, cols = s)

    const int qt = blockIdx.x;
    const int bh = blockIdx.y;
    const __half* qb = g_qh + bh * Tn * Dn;
    const __half* kb = g_kh + bh * Tn * Dn;
    const __half* vt = g_vt + bh * Dn * Tn;

    const int tid  = threadIdx.x;
    const int warp = tid >> 5, lane = tid & 31;
    const int g = lane >> 2, t4 = lane & 3;
    const int wm = warp * 32;
    const float scale = 0.05103103630798287f;   // 1/sqrt(384)

    auto load_kv = [&](int kt, int st) {
        __half* Kd = Ks + st * 64 * LDSH;
        __half* Vd = Vs + st * 64 * LDVH;
        #pragma unroll
        for (int i = 0; i < 4; i++) {
            int f = tid + i * 128;                 // 512 chunks of 16B (8 halves)
            int r = f >> 3, c = (f & 7) * 8;
            cp16h(&Kd[r * LDSH + c], &kb[(kt * 64 + r) * Dn + c]);
            cp16h(&Vd[r * LDVH + c], &vt[r * Tn + kt * 64 + c]);
        }
        CP_COMMIT;
    };

    // stage Q (plain 16B copies); start K/V pipeline
    #pragma unroll
    for (int i = 0; i < 8; i++) {
        int f = tid + i * 128;
        int r = f >> 3, c = (f & 7) * 8;
        *reinterpret_cast<float4*>(&QP[r * LDSH + c]) =
            *reinterpret_cast<const float4*>(&qb[(qt * 128 + r) * Dn + c]);
    }
    load_kv(0, 0);
    __syncthreads();

    // hoist Q fragments
    unsigned qf[4][2][4];
    #pragma unroll
    for (int kk = 0; kk < 4; kk++)
        #pragma unroll
        for (int ms = 0; ms < 2; ms++) {
            const __half* r0 = &QP[(wm + ms * 16 + g) * LDSH + kk * 16 + 2 * t4];
            const __half* r1 = r0 + 8 * LDSH;
            qf[kk][ms][0] = ldh2(r0);     qf[kk][ms][2] = ldh2(r0 + 8);
            qf[kk][ms][1] = ldh2(r1);     qf[kk][ms][3] = ldh2(r1 + 8);
        }

    float l_r[2][2] = {};    // per-thread partial row sums (reduced at epilogue)
    float o[2][8][4] = {};

    for (int kt = 0; kt < Tn / 64; kt++) {
        const int cur = kt & 1;
        CP_WAIT0;
        __syncthreads();                 // tile kt visible; prev buffer free
        if (kt + 1 < Tn / 64) load_kv(kt + 1, cur ^ 1);

        const __half* Kc = Ks + cur * 64 * LDSH;
        const __half* Vc = Vs + cur * 64 * LDVH;

        // S = Q K^T : warp m32 x n64, k64 in 4 mma-k16 steps
        float s[2][8][4] = {};
        #pragma unroll
        for (int kk = 0; kk < 4; kk++) {
            #pragma unroll
            for (int n = 0; n < 8; n++) {
                const __half* kp = &Kc[(n * 8 + g) * LDSH + kk * 16 + 2 * t4];
                unsigned b[2] = { ldh2(kp), ldh2(kp + 8) };
                mma16h(s[0][n], qf[kk][0], b);
                mma16h(s[1][n], qf[kk][1], b);
            }
        }

        // softmax numerator: p = exp(s*scale); P written as half2 (warp-private)
        #pragma unroll
        for (int ms = 0; ms < 2; ms++) {
            float rs0 = 0.f, rs1 = 0.f;
            #pragma unroll
            for (int n = 0; n < 8; n++) {
                float p0 = __expf(s[ms][n][0] * scale);
                float p1 = __expf(s[ms][n][1] * scale);
                float p2 = __expf(s[ms][n][2] * scale);
                float p3 = __expf(s[ms][n][3] * scale);
                rs0 += p0 + p1;
                rs1 += p2 + p3;
                *reinterpret_cast<__half2*>(
                    &QP[(wm + ms * 16 + g) * LDSH + n * 8 + 2 * t4]) =
                    __floats2half2_rn(p0, p1);
                *reinterpret_cast<__half2*>(
                    &QP[(wm + ms * 16 + g + 8) * LDSH + n * 8 + 2 * t4]) =
                    __floats2half2_rn(p2, p3);
            }
            l_r[ms][0] += rs0;
            l_r[ms][1] += rs1;
        }
        __syncwarp();        // P rows are warp-private: warp barrier suffices

        // O += P V : A = P[m][s], B = V[s][d] from Vt[d][s]
        #pragma unroll
        for (int kk = 0; kk < 4; kk++) {
            unsigned a[2][4];
            #pragma unroll
            for (int ms = 0; ms < 2; ms++) {
                const __half* r0 = &QP[(wm + ms * 16 + g) * LDSH + kk * 16 + 2 * t4];
                const __half* r1 = r0 + 8 * LDSH;
                a[ms][0] = ldh2(r0);     a[ms][2] = ldh2(r0 + 8);
                a[ms][1] = ldh2(r1);     a[ms][3] = ldh2(r1 + 8);
            }
            #pragma unroll
            for (int n = 0; n < 8; n++) {
                const __half* vp = &Vc[(n * 8 + g) * LDVH + kk * 16 + 2 * t4];
                unsigned b[2] = { ldh2(vp), ldh2(vp + 8) };
                mma16h(o[0][n], a[0], b);
                mma16h(o[1][n], a[1], b);
            }
        }
    }

    // epilogue: reduce l across 4-lane group, normalize, tf32-round for proj
    #pragma unroll
    for (int ms = 0; ms < 2; ms++)
        #pragma unroll
        for (int rh = 0; rh < 2; rh++) {
            float l = l_r[ms][rh];
            l += __shfl_xor_sync(0xffffffffu, l, 1);
            l += __shfl_xor_sync(0xffffffffu, l, 2);
            float inv = 1.f / l;
            int r = qt * 128 + wm + ms * 16 + rh * 8 + g;
            float* orow = g_attn + (bh * Tn + r) * Dn;
            #pragma unroll
            for (int n = 0; n < 8; n++)
                *reinterpret_cast<float2*>(&orow[n * 8 + 2 * t4]) =
                    make_float2(f2tf(o[ms][n][2 * rh] * inv),
                                f2tf(o[ms][n][2 * rh + 1] * inv));
        }
}

// ---------------------------------------------------------------------------
// Kernel 3: output projection (EXACT R10 config, tf32). Block 256m x 64n,
// 8 warps m32, cp.async 2-stage. grid = (64, 6).
// ---------------------------------------------------------------------------
__global__ void __launch_bounds__(256, 2)
proj_kernel(const float* __restrict__ bp, float* __restrict__ out)
{
    extern __shared__ __align__(16) float smp[];
    float* As = smp;                    // [2][256*LDA]
    float* Wn = smp + 2 * 256 * LDA;    // [2][64*LDA]

    const int mt = blockIdx.x;
    const int nt = blockIdx.y;
    const int tid  = threadIdx.x;
    const int warp = tid >> 5, lane = tid & 31;
    const int g = lane >> 2, t4 = lane & 3;
    const int m0 = mt * 256, n0 = nt * 64;
    const int wm = warp * 32;

    float acc[2][8][4] = {};

    auto load_stage = [&](int it, int st) {
        const int k0 = it * 32;
        const int h  = k0 >> 6;
        const int d0 = k0 & 63;
        float* Ad = As + st * 256 * LDA;
        float* Wd = Wn + st * 64 * LDA;
        #pragma unroll
        for (int i = 0; i < 8; i++) {
            int f = tid + i * 256;
            int r = f >> 3, c = (f & 7) * 4;
            int m = m0 + r, b = m >> 10, t = m & 1023;
            cp16(&Ad[r * LDA + c], &g_attn[((b * Hn + h) * Tn + t) * Dn + d0 + c]);
        }
        #pragma unroll
        for (int i = 0; i < 2; i++) {
            int f = tid + i * 256;
            int r = f >> 3, c = (f & 7) * 4;
            cp16(&Wd[r * LDA + c], &g_wpr[(n0 + r) * Cn + k0 + c]);
        }
        CP_COMMIT;
    };

    load_stage(0, 0);
    for (int it = 0; it < 12; it++) {
        const int cur = it & 1;
        CP_WAIT0;
        __syncthreads();
        if (it + 1 < 12) load_stage(it + 1, cur ^ 1);

        const float* Ac = As + cur * 256 * LDA;
        const float* Wc = Wn + cur * 64 * LDA;
        #pragma unroll
        for (int kk = 0; kk < 32; kk += 8) {
            unsigned a[2][4];
            #pragma unroll
            for (int ms = 0; ms < 2; ms++) {
                const float* Ar = &Ac[(wm + ms * 16 + g) * LDA + kk];
                a[ms][0] = fau(Ar[t4]);           a[ms][2] = fau(Ar[t4 + 4]);
                a[ms][1] = fau(Ar[8 * LDA + t4]); a[ms][3] = fau(Ar[8 * LDA + t4 + 4]);
            }
            #pragma unroll
            for (int n = 0; n < 8; n++) {
                unsigned b[2];
                b[0] = fau(Wc[(n * 8 + g) * LDA + kk + t4]);
                b[1] = fau(Wc[(n * 8 + g) * LDA + kk + t4 + 4]);
                mma8(acc[0][n], a[0], b);
                mma8(acc[1][n], a[1], b);
            }
        }
    }

    #pragma unroll
    for (int ms = 0; ms < 2; ms++)
        #pragma unroll
        for (int rh = 0; rh < 2; rh++) {
            int m = m0 + wm + ms * 16 + rh * 8 + g;
            #pragma unroll
            for (int n = 0; n < 8; n++) {
                int c = n0 + n * 8 + 2 * t4;
                *reinterpret_cast<float2*>(&out[m * Cn + c]) =
                    make_float2(acc[ms][n][2 * rh] + bp[c],
                                acc[ms][n][2 * rh + 1] + bp[c + 1]);
            }
        }
}

// ---------------------------------------------------------------------------
extern "C" void kernel_launch(void* const* d_in, const int* in_sizes, int n_in,
                              void* d_out, int out_size)
{
    const float* x  = (const float*)d_in[0];
    const float* wq = (const float*)d_in[1];
    const float* wk = (const float*)d_in[2];
    const float* wv = (const float*)d_in[3];
    const float* wp = (const float*)d_in[4];
    const float* bp = (const float*)d_in[5];
    float* out = (float*)d_out;

    round_all<<<(N4_TOT + 255) / 256, 256>>>(
        (const float4*)x, (const float4*)wq, (const float4*)wk,
        (const float4*)wv, (const float4*)wp);

    const int qkv_smem = 2 * (256 * LDA + 32 * LDB) * (int)sizeof(float);   // 92160
    cudaFuncSetAttribute(qkv_kernel,
                         cudaFuncAttributeMaxDynamicSharedMemorySize, qkv_smem);
    qkv_kernel<<<dim3(64, 18), 256, qkv_smem>>>();

    vtrans_kernel<<<dim3(Tn / 64, BH), 256>>>();

    const int attn_smem =
        (128 * LDSH + 2 * 64 * LDSH + 2 * 64 * LDVH) * (int)sizeof(__half); // 55296
    cudaFuncSetAttribute(attn_kernel,
                         cudaFuncAttributeMaxDynamicSharedMemorySize, attn_smem);
    attn_kernel<<<dim3(Tn / 128, BH), 128, attn_smem>>>();

    const int proj_smem = 2 * (256 * LDA + 64 * LDA) * (int)sizeof(float);  // 92160
    cudaFuncSetAttribute(proj_kernel,
                         cudaFuncAttributeMaxDynamicSharedMemorySize, proj_smem);
    proj_kernel<<<dim3(64, 6), 256, proj_smem>>>(bp, out);
}